// round 12
// baseline (speedup 1.0000x reference)
#include <cuda_runtime.h>
#include <cuda_bf16.h>
#include <math.h>
#include <cstdint>

// Problem constants
#define BB 4
#define SS 2048
#define DD 512
#define HH 8
#define KK 64
#define FF 64
#define MT (BB*SS)
#define EPS 1e-5f

// -------- scratch (no allocation allowed) --------
__device__ float g_v  [MT*DD];
__device__ float g_ctx[MT*DD];
__device__ float g_tmp[MT*DD];
__device__ float g_h  [MT*DD];
__device__ float g_hh [MT*FF];
__device__ __nv_bfloat16 g_qhi[MT*DD];
__device__ __nv_bfloat16 g_qlo[MT*DD];
__device__ __nv_bfloat16 g_khi[MT*DD];
__device__ __nv_bfloat16 g_klo[MT*DD];
// transposed+split weights: [N][K] bf16 hi/lo
__device__ __nv_bfloat16 g_wqt_h[DD*DD], g_wqt_l[DD*DD];
__device__ __nv_bfloat16 g_wkt_h[DD*DD], g_wkt_l[DD*DD];
__device__ __nv_bfloat16 g_wvt_h[DD*DD], g_wvt_l[DD*DD];
__device__ __nv_bfloat16 g_wot_h[DD*DD], g_wot_l[DD*DD];
__device__ __nv_bfloat16 g_w2t_h[DD*FF], g_w2t_l[DD*FF];
// V transposed+split: [bh][d=64][s=2048]
__device__ __nv_bfloat16 g_vt_h[BB*HH*KK*SS], g_vt_l[BB*HH*KK*SS];

// ======================================================================
// warp-level MMA helpers
// ======================================================================
__device__ __forceinline__ uint32_t smem_u32(const void* p) {
    uint32_t a;
    asm("{ .reg .u64 t; cvta.to.shared.u64 t, %1; cvt.u32.u64 %0, t; }"
        : "=r"(a) : "l"(p));
    return a;
}
__device__ __forceinline__ void ldsm_x4(uint32_t r[4], uint32_t addr) {
    asm volatile("ldmatrix.sync.aligned.m8n8.x4.shared.b16 {%0,%1,%2,%3}, [%4];"
        : "=r"(r[0]), "=r"(r[1]), "=r"(r[2]), "=r"(r[3]) : "r"(addr));
}
__device__ __forceinline__ void ldsm_x2(uint32_t r[2], uint32_t addr) {
    asm volatile("ldmatrix.sync.aligned.m8n8.x2.shared.b16 {%0,%1}, [%2];"
        : "=r"(r[0]), "=r"(r[1]) : "r"(addr));
}
__device__ __forceinline__ void mma_bf16(float d[4], const uint32_t a[4],
                                         const uint32_t b[2]) {
    asm volatile("mma.sync.aligned.m16n8k16.row.col.f32.bf16.bf16.f32 "
        "{%0,%1,%2,%3}, {%4,%5,%6,%7}, {%8,%9}, {%0,%1,%2,%3};"
        : "+f"(d[0]), "+f"(d[1]), "+f"(d[2]), "+f"(d[3])
        : "r"(a[0]), "r"(a[1]), "r"(a[2]), "r"(a[3]), "r"(b[0]), "r"(b[1]));
}
__device__ __forceinline__ void split2(float v, __nv_bfloat16& h, __nv_bfloat16& l) {
    h = __float2bfloat16(v);
    l = __float2bfloat16(v - __bfloat162float(h));
}

// fast exp on FMA/ALU pipes (no MUFU)
__device__ __forceinline__ float fast_exp(float x) {
    x = fmaxf(x, -87.0f);
    float y0 = x * 1.4426950408889634f;
    float z  = y0 + 12582912.0f;
    float t  = z - 12582912.0f;
    float f  = y0 - t;
    int   n  = __float_as_int(z) - 0x4B400000;
    float p  = 0.0013333558f;
    p = fmaf(p, f, 0.0096181291f);
    p = fmaf(p, f, 0.0555041087f);
    p = fmaf(p, f, 0.2402265069f);
    p = fmaf(p, f, 0.6931471806f);
    p = fmaf(p, f, 1.0f);
    return p * __int_as_float((n + 127) << 23);
}

// ======================================================================
// weight split-transpose: W[K][N] fp32 -> Wt hi/lo [N][K] bf16
// ======================================================================
__global__ void __launch_bounds__(256)
split_wt(const float* __restrict__ W,
         __nv_bfloat16* __restrict__ th,
         __nv_bfloat16* __restrict__ tl,
         int Kd, int N) {
    __shared__ float tile[64][65];
    const int tid = threadIdx.x;
    const int k0 = blockIdx.x * 64, n0 = blockIdx.y * 64;
    #pragma unroll
    for (int i = 0; i < 16; i++) {
        int lin = tid + i * 256;
        int r = lin >> 6, c = lin & 63;
        tile[r][c] = W[(size_t)(k0 + r) * N + n0 + c];
    }
    __syncthreads();
    #pragma unroll
    for (int i = 0; i < 8; i++) {
        int lin = tid + i * 256;
        int n = lin >> 5, k2 = (lin & 31) * 2;
        float v0 = tile[k2][n], v1 = tile[k2 + 1][n];
        __nv_bfloat16 h0, l0, h1, l1;
        split2(v0, h0, l0); split2(v1, h1, l1);
        size_t o = (size_t)(n0 + n) * Kd + k0 + k2;
        *(__nv_bfloat162*)&th[o] = {h0, h1};
        *(__nv_bfloat162*)&tl[o] = {l0, l1};
    }
}

// ======================================================================
// V split-transpose: per (b,h): V[s][d] -> vt hi/lo [bh][d][s]
// ======================================================================
__global__ void __launch_bounds__(256)
v_split_t(const float* __restrict__ v,
          __nv_bfloat16* __restrict__ th,
          __nv_bfloat16* __restrict__ tl) {
    __shared__ float tile[64][65];
    const int tid = threadIdx.x;
    const int bh = blockIdx.x, b = bh >> 3, h = bh & 7;
    const int s0 = blockIdx.y * 64;
    #pragma unroll
    for (int i = 0; i < 16; i++) {
        int lin = tid + i * 256;
        int r = lin >> 6, c = lin & 63;
        tile[r][c] = v[(size_t)(b * SS + s0 + r) * DD + h * KK + c];
    }
    __syncthreads();
    #pragma unroll
    for (int i = 0; i < 8; i++) {
        int lin = tid + i * 256;
        int d = lin >> 5, s2 = (lin & 31) * 2;
        float v0 = tile[s2][d], v1 = tile[s2 + 1][d];
        __nv_bfloat16 h0, l0, h1, l1;
        split2(v0, h0, l0); split2(v1, h1, l1);
        size_t o = ((size_t)bh * KK + d) * SS + s0 + s2;
        *(__nv_bfloat162*)&th[o] = {h0, h1};
        *(__nv_bfloat162*)&tl[o] = {l0, l1};
    }
}

// ======================================================================
// gemm_hmma: C[M,N] = A @ Wt^T + bias (fp32 out)   [proven R11 kernel]
// ======================================================================
__global__ void __launch_bounds__(256)
gemm_hmma(const float* __restrict__ A,
          const __nv_bfloat16* __restrict__ Bth,
          const __nv_bfloat16* __restrict__ Btl,
          const float* __restrict__ bias,
          float* __restrict__ C,
          int M, int N, int Kd) {
    __shared__ __nv_bfloat16 sAh[128 * 40], sAl[128 * 40];
    __shared__ __nv_bfloat16 sBh[128 * 40], sBl[128 * 40];

    const int tid = threadIdx.x, wid = tid >> 5, lane = tid & 31;
    const int m0 = blockIdx.y * 128, n0 = blockIdx.x * 128;
    const int wm = (wid >> 2) * 64, wn = (wid & 3) * 32;
    const int la16 = lane & 15;

    float acc[4][4][4];
    #pragma unroll
    for (int mt = 0; mt < 4; mt++)
        #pragma unroll
        for (int nt = 0; nt < 4; nt++)
            #pragma unroll
            for (int e = 0; e < 4; e++) acc[mt][nt][e] = 0.f;

    const uint32_t sAhB = smem_u32(sAh), sAlB = smem_u32(sAl);
    const uint32_t sBhB = smem_u32(sBh), sBlB = smem_u32(sBl);
    const uint32_t a_off = (uint32_t)((wm + la16) * 80 + (lane >> 4) * 16);
    const uint32_t b_off = (uint32_t)((wn + (la16 & 7)) * 80 + ((la16 >> 3) & 1) * 16);

    for (int kt = 0; kt < Kd; kt += 32) {
        #pragma unroll
        for (int i = 0; i < 4; i++) {
            int idx = tid + i * 256;
            int row = idx >> 3, c4 = (idx & 7) * 4;
            float4 av = *(const float4*)&A[(size_t)(m0 + row) * Kd + kt + c4];
            __nv_bfloat16 hx, lx, hy, ly, hz, lz, hw, lw;
            split2(av.x, hx, lx); split2(av.y, hy, ly);
            split2(av.z, hz, lz); split2(av.w, hw, lw);
            int so = row * 40 + c4;
            *(__nv_bfloat162*)&sAh[so]     = {hx, hy};
            *(__nv_bfloat162*)&sAh[so + 2] = {hz, hw};
            *(__nv_bfloat162*)&sAl[so]     = {lx, ly};
            *(__nv_bfloat162*)&sAl[so + 2] = {lz, lw};
        }
        #pragma unroll
        for (int i = 0; i < 2; i++) {
            int idx = tid + i * 256;
            int row = idx >> 2, c8 = (idx & 3) * 8;
            size_t go = (size_t)(n0 + row) * Kd + kt + c8;
            *(uint4*)&sBh[row * 40 + c8] = *(const uint4*)&Bth[go];
            *(uint4*)&sBl[row * 40 + c8] = *(const uint4*)&Btl[go];
        }
        __syncthreads();

        #pragma unroll
        for (int ks = 0; ks < 2; ks++) {
            const uint32_t kbyte = ks * 32;
            uint32_t af[4][4], bh_[4][2], bl_[4][2];
            #pragma unroll
            for (int mt = 0; mt < 4; mt++)
                ldsm_x4(af[mt], sAhB + a_off + mt * 16 * 80 + kbyte);
            #pragma unroll
            for (int nt = 0; nt < 4; nt++) {
                ldsm_x2(bh_[nt], sBhB + b_off + nt * 8 * 80 + kbyte);
                ldsm_x2(bl_[nt], sBlB + b_off + nt * 8 * 80 + kbyte);
            }
            #pragma unroll
            for (int mt = 0; mt < 4; mt++)
                #pragma unroll
                for (int nt = 0; nt < 4; nt++) {
                    mma_bf16(acc[mt][nt], af[mt], bh_[nt]);
                    mma_bf16(acc[mt][nt], af[mt], bl_[nt]);
                }
            #pragma unroll
            for (int mt = 0; mt < 4; mt++)
                ldsm_x4(af[mt], sAlB + a_off + mt * 16 * 80 + kbyte);
            #pragma unroll
            for (int mt = 0; mt < 4; mt++)
                #pragma unroll
                for (int nt = 0; nt < 4; nt++)
                    mma_bf16(acc[mt][nt], af[mt], bh_[nt]);
        }
        __syncthreads();
    }

    const int rq = lane >> 2, cq = (lane & 3) * 2;
    #pragma unroll
    for (int mt = 0; mt < 4; mt++) {
        #pragma unroll
        for (int nt = 0; nt < 4; nt++) {
            int row = m0 + wm + mt * 16 + rq;
            int col = n0 + wn + nt * 8 + cq;
            float b0 = bias[col], b1 = bias[col + 1];
            *(float2*)&C[(size_t)row * N + col] =
                make_float2(acc[mt][nt][0] + b0, acc[mt][nt][1] + b1);
            *(float2*)&C[(size_t)(row + 8) * N + col] =
                make_float2(acc[mt][nt][2] + b0, acc[mt][nt][3] + b1);
        }
    }
}

// ======================================================================
// gemm_hmma_qk: same GEMM but epilogue writes (acc+bias)*scale split into
// bf16 hi/lo directly (for Q with scale=1/8, K with scale=1).
// ======================================================================
__global__ void __launch_bounds__(256)
gemm_hmma_qk(const float* __restrict__ A,
             const __nv_bfloat16* __restrict__ Bth,
             const __nv_bfloat16* __restrict__ Btl,
             const float* __restrict__ bias,
             __nv_bfloat16* __restrict__ Oh,
             __nv_bfloat16* __restrict__ Ol,
             int M, int N, int Kd, float scale) {
    __shared__ __nv_bfloat16 sAh[128 * 40], sAl[128 * 40];
    __shared__ __nv_bfloat16 sBh[128 * 40], sBl[128 * 40];

    const int tid = threadIdx.x, wid = tid >> 5, lane = tid & 31;
    const int m0 = blockIdx.y * 128, n0 = blockIdx.x * 128;
    const int wm = (wid >> 2) * 64, wn = (wid & 3) * 32;
    const int la16 = lane & 15;

    float acc[4][4][4];
    #pragma unroll
    for (int mt = 0; mt < 4; mt++)
        #pragma unroll
        for (int nt = 0; nt < 4; nt++)
            #pragma unroll
            for (int e = 0; e < 4; e++) acc[mt][nt][e] = 0.f;

    const uint32_t sAhB = smem_u32(sAh), sAlB = smem_u32(sAl);
    const uint32_t sBhB = smem_u32(sBh), sBlB = smem_u32(sBl);
    const uint32_t a_off = (uint32_t)((wm + la16) * 80 + (lane >> 4) * 16);
    const uint32_t b_off = (uint32_t)((wn + (la16 & 7)) * 80 + ((la16 >> 3) & 1) * 16);

    for (int kt = 0; kt < Kd; kt += 32) {
        #pragma unroll
        for (int i = 0; i < 4; i++) {
            int idx = tid + i * 256;
            int row = idx >> 3, c4 = (idx & 7) * 4;
            float4 av = *(const float4*)&A[(size_t)(m0 + row) * Kd + kt + c4];
            __nv_bfloat16 hx, lx, hy, ly, hz, lz, hw, lw;
            split2(av.x, hx, lx); split2(av.y, hy, ly);
            split2(av.z, hz, lz); split2(av.w, hw, lw);
            int so = row * 40 + c4;
            *(__nv_bfloat162*)&sAh[so]     = {hx, hy};
            *(__nv_bfloat162*)&sAh[so + 2] = {hz, hw};
            *(__nv_bfloat162*)&sAl[so]     = {lx, ly};
            *(__nv_bfloat162*)&sAl[so + 2] = {lz, lw};
        }
        #pragma unroll
        for (int i = 0; i < 2; i++) {
            int idx = tid + i * 256;
            int row = idx >> 2, c8 = (idx & 3) * 8;
            size_t go = (size_t)(n0 + row) * Kd + kt + c8;
            *(uint4*)&sBh[row * 40 + c8] = *(const uint4*)&Bth[go];
            *(uint4*)&sBl[row * 40 + c8] = *(const uint4*)&Btl[go];
        }
        __syncthreads();

        #pragma unroll
        for (int ks = 0; ks < 2; ks++) {
            const uint32_t kbyte = ks * 32;
            uint32_t af[4][4], bh_[4][2], bl_[4][2];
            #pragma unroll
            for (int mt = 0; mt < 4; mt++)
                ldsm_x4(af[mt], sAhB + a_off + mt * 16 * 80 + kbyte);
            #pragma unroll
            for (int nt = 0; nt < 4; nt++) {
                ldsm_x2(bh_[nt], sBhB + b_off + nt * 8 * 80 + kbyte);
                ldsm_x2(bl_[nt], sBlB + b_off + nt * 8 * 80 + kbyte);
            }
            #pragma unroll
            for (int mt = 0; mt < 4; mt++)
                #pragma unroll
                for (int nt = 0; nt < 4; nt++) {
                    mma_bf16(acc[mt][nt], af[mt], bh_[nt]);
                    mma_bf16(acc[mt][nt], af[mt], bl_[nt]);
                }
            #pragma unroll
            for (int mt = 0; mt < 4; mt++)
                ldsm_x4(af[mt], sAlB + a_off + mt * 16 * 80 + kbyte);
            #pragma unroll
            for (int mt = 0; mt < 4; mt++)
                #pragma unroll
                for (int nt = 0; nt < 4; nt++)
                    mma_bf16(acc[mt][nt], af[mt], bh_[nt]);
        }
        __syncthreads();
    }

    const int rq = lane >> 2, cq = (lane & 3) * 2;
    #pragma unroll
    for (int mt = 0; mt < 4; mt++) {
        #pragma unroll
        for (int nt = 0; nt < 4; nt++) {
            int row = m0 + wm + mt * 16 + rq;
            int col = n0 + wn + nt * 8 + cq;
            float b0 = bias[col], b1 = bias[col + 1];
            float v0 = (acc[mt][nt][0] + b0) * scale;
            float v1 = (acc[mt][nt][1] + b1) * scale;
            float v2 = (acc[mt][nt][2] + b0) * scale;
            float v3 = (acc[mt][nt][3] + b1) * scale;
            __nv_bfloat16 h0, l0, h1, l1;
            split2(v0, h0, l0); split2(v1, h1, l1);
            *(__nv_bfloat162*)&Oh[(size_t)row * N + col] = {h0, h1};
            *(__nv_bfloat162*)&Ol[(size_t)row * N + col] = {l0, l1};
            split2(v2, h0, l0); split2(v3, h1, l1);
            *(__nv_bfloat162*)&Oh[(size_t)(row + 8) * N + col] = {h0, h1};
            *(__nv_bfloat162*)&Ol[(size_t)(row + 8) * N + col] = {l0, l1};
        }
    }
}

// ======================================================================
// attn_fused: per CTA = one (b,h) x 128 q rows.
// Pass 1: 3-term HMMA scores over 16 K-tiles, exact running row max+sum.
// Pass 2: recompute scores, p = exp(s-m)/sum -> write atn + stage bf16
//         hi/lo in smem -> HMMA ctx accumulate with pre-transposed V.
// ======================================================================
#define QKST 72
#define QKSB 144
#define PVST 136
#define PVSB 272
#define AT_SMEM ((4*128*QKST + 2*64*PVST + 2*128*PVST) * 2 + (128 + 128 + 512) * 4)

__global__ void __launch_bounds__(256)
attn_fused(const __nv_bfloat16* __restrict__ qhi,
           const __nv_bfloat16* __restrict__ qlo,
           const __nv_bfloat16* __restrict__ khi,
           const __nv_bfloat16* __restrict__ klo,
           const __nv_bfloat16* __restrict__ vth,
           const __nv_bfloat16* __restrict__ vtl,
           float* __restrict__ atn,
           float* __restrict__ ctx) {
    extern __shared__ char smraw[];
    __nv_bfloat16* sQh = (__nv_bfloat16*)smraw;
    __nv_bfloat16* sQl = sQh + 128 * QKST;
    __nv_bfloat16* sKh = sQl + 128 * QKST;
    __nv_bfloat16* sKl = sKh + 128 * QKST;
    __nv_bfloat16* sVh = sKl + 128 * QKST;
    __nv_bfloat16* sVl = sVh + 64 * PVST;
    __nv_bfloat16* sPh = sVl + 64 * PVST;
    __nv_bfloat16* sPl = sPh + 128 * PVST;
    float* sm_m = (float*)(sPl + 128 * PVST);
    float* sm_s = sm_m + 128;
    float* sm_p = sm_s + 128;               // 4 x 128 partials

    const int tid = threadIdx.x, wid = tid >> 5, lane = tid & 31;
    const int bh = blockIdx.y, b = bh >> 3, h = bh & 7;
    const int q0 = blockIdx.x * 128;
    const int la16 = lane & 15;
    const int rq = lane >> 2, cq = (lane & 3) * 2;

    if (tid < 128) { sm_m[tid] = -1e30f; sm_s[tid] = 0.f; }

    // load Q tile (once)
    #pragma unroll
    for (int i = 0; i < 4; i++) {
        int idx = tid + i * 256;
        int row = idx >> 3, c8 = idx & 7;
        int soff = row * QKST + c8 * 8;
        size_t qg = (size_t)(b * SS + q0 + row) * DD + h * KK + c8 * 8;
        *(uint4*)&sQh[soff] = *(const uint4*)&qhi[qg];
        *(uint4*)&sQl[soff] = *(const uint4*)&qlo[qg];
    }

    // score warp mapping: 8 warps, 2x4, each 64(q) x 32(k)
    const int wr = wid >> 2, wc = wid & 3;
    const int wm = wr * 64, wn = wc * 32;
    const uint32_t qhiA = smem_u32(sQh), qloA = smem_u32(sQl);
    const uint32_t khiA = smem_u32(sKh), kloA = smem_u32(sKl);
    const uint32_t a_off = (uint32_t)((wm + la16) * QKSB + (lane >> 4) * 16);
    const uint32_t b_off = (uint32_t)((wn + (la16 & 7)) * QKSB + ((la16 >> 3) & 1) * 16);
    const uint32_t qbases[3] = {qhiA, qhiA, qloA};
    const uint32_t kbases[3] = {khiA, kloA, khiA};

    float acc[4][4][4];

    // ---------------- pass 1: row max + exp-sum ----------------
    for (int t = 0; t < 16; t++) {
        __syncthreads();
        #pragma unroll
        for (int i = 0; i < 4; i++) {
            int idx = tid + i * 256;
            int row = idx >> 3, c8 = idx & 7;
            int soff = row * QKST + c8 * 8;
            size_t kg = (size_t)(b * SS + t * 128 + row) * DD + h * KK + c8 * 8;
            *(uint4*)&sKh[soff] = *(const uint4*)&khi[kg];
            *(uint4*)&sKl[soff] = *(const uint4*)&klo[kg];
        }
        __syncthreads();

        #pragma unroll
        for (int mt = 0; mt < 4; mt++)
            #pragma unroll
            for (int nt = 0; nt < 4; nt++)
                #pragma unroll
                for (int e = 0; e < 4; e++) acc[mt][nt][e] = 0.f;
        #pragma unroll
        for (int trm = 0; trm < 3; trm++) {
            #pragma unroll
            for (int kkt = 0; kkt < 4; kkt++) {
                const uint32_t kbyte = kkt * 32;
                uint32_t afrag[4][4], bfrag[4][2];
                #pragma unroll
                for (int mt = 0; mt < 4; mt++)
                    ldsm_x4(afrag[mt], qbases[trm] + a_off + mt * 16 * QKSB + kbyte);
                #pragma unroll
                for (int nt = 0; nt < 4; nt++)
                    ldsm_x2(bfrag[nt], kbases[trm] + b_off + nt * 8 * QKSB + kbyte);
                #pragma unroll
                for (int mt = 0; mt < 4; mt++)
                    #pragma unroll
                    for (int nt = 0; nt < 4; nt++)
                        mma_bf16(acc[mt][nt], afrag[mt], bfrag[nt]);
            }
        }

        // local row max (over warp's 32 cols)
        #pragma unroll
        for (int mt = 0; mt < 4; mt++) {
            float l0 = -1e30f, l1 = -1e30f;
            #pragma unroll
            for (int nt = 0; nt < 4; nt++) {
                l0 = fmaxf(l0, fmaxf(acc[mt][nt][0], acc[mt][nt][1]));
                l1 = fmaxf(l1, fmaxf(acc[mt][nt][2], acc[mt][nt][3]));
            }
            l0 = fmaxf(l0, __shfl_xor_sync(0xffffffff, l0, 1));
            l0 = fmaxf(l0, __shfl_xor_sync(0xffffffff, l0, 2));
            l1 = fmaxf(l1, __shfl_xor_sync(0xffffffff, l1, 1));
            l1 = fmaxf(l1, __shfl_xor_sync(0xffffffff, l1, 2));
            if ((lane & 3) == 0) {
                sm_p[wc * 128 + wm + mt * 16 + rq]     = l0;
                sm_p[wc * 128 + wm + mt * 16 + rq + 8] = l1;
            }
        }
        __syncthreads();
        if (tid < 128) {
            float tm = fmaxf(fmaxf(sm_p[tid], sm_p[128 + tid]),
                             fmaxf(sm_p[256 + tid], sm_p[384 + tid]));
            float mo = sm_m[tid];
            float mn = fmaxf(mo, tm);
            sm_m[tid] = mn;
            sm_s[tid] *= fast_exp(mo - mn);
        }
        __syncthreads();
        // exp sums
        #pragma unroll
        for (int mt = 0; mt < 4; mt++) {
            int r0 = wm + mt * 16 + rq;
            float m0 = sm_m[r0], m1 = sm_m[r0 + 8];
            float s0 = 0.f, s1 = 0.f;
            #pragma unroll
            for (int nt = 0; nt < 4; nt++) {
                s0 += fast_exp(acc[mt][nt][0] - m0) + fast_exp(acc[mt][nt][1] - m0);
                s1 += fast_exp(acc[mt][nt][2] - m1) + fast_exp(acc[mt][nt][3] - m1);
            }
            s0 += __shfl_xor_sync(0xffffffff, s0, 1);
            s0 += __shfl_xor_sync(0xffffffff, s0, 2);
            s1 += __shfl_xor_sync(0xffffffff, s1, 1);
            s1 += __shfl_xor_sync(0xffffffff, s1, 2);
            if ((lane & 3) == 0) {
                sm_p[wc * 128 + r0]     = s0;
                sm_p[wc * 128 + r0 + 8] = s1;
            }
        }
        __syncthreads();
        if (tid < 128)
            sm_s[tid] += sm_p[tid] + sm_p[128 + tid] + sm_p[256 + tid] + sm_p[384 + tid];
    }
    __syncthreads();
    if (tid < 128) sm_s[tid] = 1.f / sm_s[tid];
    __syncthreads();

    // cache final m / inv per thread (score-layout rows)
    float cm[4][2], ci[4][2];
    #pragma unroll
    for (int mt = 0; mt < 4; mt++) {
        int r0 = wm + mt * 16 + rq;
        cm[mt][0] = sm_m[r0];     cm[mt][1] = sm_m[r0 + 8];
        ci[mt][0] = sm_s[r0];     ci[mt][1] = sm_s[r0 + 8];
    }

    // ctx warp mapping: 8 warps 4x2, each 32(q) x 32(d)
    const int wm2 = (wid >> 1) * 32, wn2 = (wid & 1) * 32;
    const uint32_t sPhB = smem_u32(sPh), sPlB = smem_u32(sPl);
    const uint32_t sVhB = smem_u32(sVh), sVlB = smem_u32(sVl);
    const uint32_t a2_off = (uint32_t)((wm2 + la16) * PVSB + (lane >> 4) * 16);
    const uint32_t b2_off = (uint32_t)((wn2 + (la16 & 7)) * PVSB + ((la16 >> 3) & 1) * 16);

    float cacc[2][4][4];
    #pragma unroll
    for (int mt = 0; mt < 2; mt++)
        #pragma unroll
        for (int nt = 0; nt < 4; nt++)
            #pragma unroll
            for (int e = 0; e < 4; e++) cacc[mt][nt][e] = 0.f;

    const size_t abase = (size_t)(h * BB + b) * SS * SS;
    const size_t vbase = (size_t)bh * KK * SS;

    // ---------------- pass 2: probs out + ctx ----------------
    for (int t = 0; t < 16; t++) {
        __syncthreads();
        #pragma unroll
        for (int i = 0; i < 4; i++) {
            int idx = tid + i * 256;
            int row = idx >> 3, c8 = idx & 7;
            int soff = row * QKST + c8 * 8;
            size_t kg = (size_t)(b * SS + t * 128 + row) * DD + h * KK + c8 * 8;
            *(uint4*)&sKh[soff] = *(const uint4*)&khi[kg];
            *(uint4*)&sKl[soff] = *(const uint4*)&klo[kg];
        }
        #pragma unroll
        for (int i = 0; i < 4; i++) {
            int idx = tid + i * 256;
            int row = idx >> 4, c16 = idx & 15;
            int soff = row * PVST + c16 * 8;
            size_t vg = vbase + (size_t)row * SS + t * 128 + c16 * 8;
            *(uint4*)&sVh[soff] = *(const uint4*)&vth[vg];
            *(uint4*)&sVl[soff] = *(const uint4*)&vtl[vg];
        }
        __syncthreads();

        #pragma unroll
        for (int mt = 0; mt < 4; mt++)
            #pragma unroll
            for (int nt = 0; nt < 4; nt++)
                #pragma unroll
                for (int e = 0; e < 4; e++) acc[mt][nt][e] = 0.f;
        #pragma unroll
        for (int trm = 0; trm < 3; trm++) {
            #pragma unroll
            for (int kkt = 0; kkt < 4; kkt++) {
                const uint32_t kbyte = kkt * 32;
                uint32_t afrag[4][4], bfrag[4][2];
                #pragma unroll
                for (int mt = 0; mt < 4; mt++)
                    ldsm_x4(afrag[mt], qbases[trm] + a_off + mt * 16 * QKSB + kbyte);
                #pragma unroll
                for (int nt = 0; nt < 4; nt++)
                    ldsm_x2(bfrag[nt], kbases[trm] + b_off + nt * 8 * QKSB + kbyte);
                #pragma unroll
                for (int mt = 0; mt < 4; mt++)
                    #pragma unroll
                    for (int nt = 0; nt < 4; nt++)
                        mma_bf16(acc[mt][nt], afrag[mt], bfrag[nt]);
            }
        }

        // probs: write to atn + stage hi/lo in smem
        #pragma unroll
        for (int mt = 0; mt < 4; mt++) {
            #pragma unroll
            for (int nt = 0; nt < 4; nt++) {
                float p00 = fast_exp(acc[mt][nt][0] - cm[mt][0]) * ci[mt][0];
                float p01 = fast_exp(acc[mt][nt][1] - cm[mt][0]) * ci[mt][0];
                float p10 = fast_exp(acc[mt][nt][2] - cm[mt][1]) * ci[mt][1];
                float p11 = fast_exp(acc[mt][nt][3] - cm[mt][1]) * ci[mt][1];
                int srow = wm + mt * 16 + rq;
                int scol = wn + nt * 8 + cq;
                size_t ga = abase + (size_t)(q0 + srow) * SS + t * 128 + scol;
                *(float2*)&atn[ga]          = make_float2(p00, p01);
                *(float2*)&atn[ga + 8 * SS] = make_float2(p10, p11);
                __nv_bfloat16 h0, l0, h1, l1;
                split2(p00, h0, l0); split2(p01, h1, l1);
                *(__nv_bfloat162*)&sPh[srow * PVST + scol] = {h0, h1};
                *(__nv_bfloat162*)&sPl[srow * PVST + scol] = {l0, l1};
                split2(p10, h0, l0); split2(p11, h1, l1);
                *(__nv_bfloat162*)&sPh[(srow + 8) * PVST + scol] = {h0, h1};
                *(__nv_bfloat162*)&sPl[(srow + 8) * PVST + scol] = {l0, l1};
            }
        }
        __syncthreads();

        // ctx accumulate: 128-deep k (s), 8 k-steps
        #pragma unroll
        for (int ks = 0; ks < 8; ks++) {
            const uint32_t kbyte = ks * 32;
            uint32_t aph[2][4], apl[2][4], bvh[4][2], bvl[4][2];
            #pragma unroll
            for (int mt = 0; mt < 2; mt++) {
                ldsm_x4(aph[mt], sPhB + a2_off + mt * 16 * PVSB + kbyte);
                ldsm_x4(apl[mt], sPlB + a2_off + mt * 16 * PVSB + kbyte);
            }
            #pragma unroll
            for (int nt = 0; nt < 4; nt++) {
                ldsm_x2(bvh[nt], sVhB + b2_off + nt * 8 * PVSB + kbyte);
                ldsm_x2(bvl[nt], sVlB + b2_off + nt * 8 * PVSB + kbyte);
            }
            #pragma unroll
            for (int mt = 0; mt < 2; mt++)
                #pragma unroll
                for (int nt = 0; nt < 4; nt++) {
                    mma_bf16(cacc[mt][nt], aph[mt], bvh[nt]);
                    mma_bf16(cacc[mt][nt], apl[mt], bvh[nt]);
                    mma_bf16(cacc[mt][nt], aph[mt], bvl[nt]);
                }
        }
    }

    // ctx epilogue
    #pragma unroll
    for (int mt = 0; mt < 2; mt++) {
        #pragma unroll
        for (int nt = 0; nt < 4; nt++) {
            int row = b * SS + q0 + wm2 + mt * 16 + rq;
            int col = h * KK + wn2 + nt * 8 + cq;
            *(float2*)&ctx[(size_t)row * DD + col] =
                make_float2(cacc[mt][nt][0], cacc[mt][nt][1]);
            *(float2*)&ctx[(size_t)(row + 8) * DD + col] =
                make_float2(cacc[mt][nt][2], cacc[mt][nt][3]);
        }
    }
}

// ======================================================================
// FFN1 GEMM + ReLU (FFMA, small)
// ======================================================================
__global__ void __launch_bounds__(256)
ffn1_gemm(const float* __restrict__ A,
          const float* __restrict__ W,
          const float* __restrict__ bias,
          float* __restrict__ C) {
    __shared__ __align__(16) float As[32 * 132];
    __shared__ __align__(16) float Ws[32 * 64];

    const int tid = threadIdx.x;
    const int m0  = blockIdx.x * 128;
    const int tq = tid >> 4;
    const int td = tid & 15;

    float acc[8][4];
    #pragma unroll
    for (int i = 0; i < 8; i++)
        #pragma unroll
        for (int j = 0; j < 4; j++) acc[i][j] = 0.f;

    for (int c = 0; c < DD; c += 32) {
        __syncthreads();
        #pragma unroll
        for (int i = 0; i < 4; i++) {
            int lin = tid + i * 256;
            int qr = lin >> 3, k4 = (lin & 7) * 4;
            float4 av = *(const float4*)&A[(size_t)(m0 + qr) * DD + c + k4];
            As[(k4 + 0) * 132 + qr] = av.x;
            As[(k4 + 1) * 132 + qr] = av.y;
            As[(k4 + 2) * 132 + qr] = av.z;
            As[(k4 + 3) * 132 + qr] = av.w;
        }
        #pragma unroll
        for (int i = 0; i < 2; i++) {
            int lin = tid + i * 256;
            int kr = lin >> 4, n4 = (lin & 15) * 4;
            *(float4*)&Ws[kr * 64 + n4] = *(const float4*)&W[(size_t)(c + kr) * FF + n4];
        }
        __syncthreads();

        #pragma unroll 8
        for (int s = 0; s < 32; s++) {
            float4 m0v = *(const float4*)&As[s * 132 + tq * 8];
            float4 m1v = *(const float4*)&As[s * 132 + tq * 8 + 4];
            float4 n0v = *(const float4*)&Ws[s * 64 + td * 4];
            float ma[8] = {m0v.x, m0v.y, m0v.z, m0v.w, m1v.x, m1v.y, m1v.z, m1v.w};
            float na[4] = {n0v.x, n0v.y, n0v.z, n0v.w};
            #pragma unroll
            for (int i = 0; i < 8; i++)
                #pragma unroll
                for (int j = 0; j < 4; j++)
                    acc[i][j] = fmaf(ma[i], na[j], acc[i][j]);
        }
    }

    float4 bv = *(const float4*)&bias[td * 4];
    float ba[4] = {bv.x, bv.y, bv.z, bv.w};
    #pragma unroll
    for (int i = 0; i < 8; i++) {
        float4 o = {fmaxf(acc[i][0] + ba[0], 0.f), fmaxf(acc[i][1] + ba[1], 0.f),
                    fmaxf(acc[i][2] + ba[2], 0.f), fmaxf(acc[i][3] + ba[3], 0.f)};
        *(float4*)&C[(size_t)(m0 + tq * 8 + i) * FF + td * 4] = o;
    }
}

// ======================================================================
// reductions + LN kernels
// ======================================================================
__device__ __forceinline__ float blockReduceSum256(float v, float* red) {
    #pragma unroll
    for (int o = 16; o; o >>= 1) v += __shfl_xor_sync(0xffffffff, v, o);
    int w = threadIdx.x >> 5;
    if ((threadIdx.x & 31) == 0) red[w] = v;
    __syncthreads();
    float r = 0.f;
    if (threadIdx.x < 32) {
        r = (threadIdx.x < 8) ? red[threadIdx.x] : 0.f;
        #pragma unroll
        for (int o = 4; o; o >>= 1) r += __shfl_xor_sync(0xffffffff, r, o);
        if (threadIdx.x == 0) red[0] = r;
    }
    __syncthreads();
    float out = red[0];
    __syncthreads();
    return out;
}

__global__ void addln2_kernel(const float* __restrict__ tmp,
                              const float* __restrict__ x,
                              const float* __restrict__ gm, const float* __restrict__ bm,
                              const float* __restrict__ g1, const float* __restrict__ b1,
                              float* __restrict__ hout) {
    __shared__ float red[32];
    const int r = blockIdx.x;
    const int d0 = threadIdx.x, d1 = threadIdx.x + 256;
    size_t base = (size_t)r * DD;

    float x0 = x[base + d0], x1 = x[base + d1];
    float p0 = tmp[base + d0] + x0;
    float p1 = tmp[base + d1] + x1;

    float mean = blockReduceSum256(p0 + p1, red) * (1.f / DD);
    float dv0 = p0 - mean, dv1 = p1 - mean;
    float var = blockReduceSum256(dv0 * dv0 + dv1 * dv1, red) * (1.f / DD);
    float rstd = rsqrtf(var + EPS);

    float m0 = dv0 * rstd * gm[d0] + bm[d0];
    float m1 = dv1 * rstd * gm[d1] + bm[d1];

    float t0 = m0 + x0, t1 = m1 + x1;
    float mean2 = blockReduceSum256(t0 + t1, red) * (1.f / DD);
    float e0 = t0 - mean2, e1 = t1 - mean2;
    float var2 = blockReduceSum256(e0 * e0 + e1 * e1, red) * (1.f / DD);
    float rstd2 = rsqrtf(var2 + EPS);

    hout[base + d0] = e0 * rstd2 * g1[d0] + b1[d0];
    hout[base + d1] = e1 * rstd2 * g1[d1] + b1[d1];
}

__global__ void addln1_kernel(const float* __restrict__ tmp,
                              const float* __restrict__ h,
                              const float* __restrict__ g, const float* __restrict__ b,
                              float* __restrict__ out) {
    __shared__ float red[32];
    const int r = blockIdx.x;
    const int d0 = threadIdx.x, d1 = threadIdx.x + 256;
    size_t base = (size_t)r * DD;

    float v0 = tmp[base + d0] + h[base + d0];
    float v1 = tmp[base + d1] + h[base + d1];

    float mean = blockReduceSum256(v0 + v1, red) * (1.f / DD);
    float e0 = v0 - mean, e1 = v1 - mean;
    float var = blockReduceSum256(e0 * e0 + e1 * e1, red) * (1.f / DD);
    float rstd = rsqrtf(var + EPS);

    out[base + d0] = e0 * rstd * g[d0] + b[d0];
    out[base + d1] = e1 * rstd * g[d1] + b[d1];
}

// ======================================================================
// launch
// ======================================================================
extern "C" void kernel_launch(void* const* d_in, const int* in_sizes, int n_in,
                              void* d_out, int out_size) {
    const float* x      = (const float*)d_in[0];
    const float* Wq     = (const float*)d_in[1];
    const float* bq     = (const float*)d_in[2];
    const float* Wk     = (const float*)d_in[3];
    const float* bk     = (const float*)d_in[4];
    const float* Wv     = (const float*)d_in[5];
    const float* bv     = (const float*)d_in[6];
    const float* Wo     = (const float*)d_in[7];
    const float* bo     = (const float*)d_in[8];
    const float* g_mha  = (const float*)d_in[9];
    const float* b_mha  = (const float*)d_in[10];
    const float* g_net1 = (const float*)d_in[11];
    const float* b_net1 = (const float*)d_in[12];
    const float* W1     = (const float*)d_in[13];
    const float* b1     = (const float*)d_in[14];
    const float* W2     = (const float*)d_in[15];
    const float* b2     = (const float*)d_in[16];
    const float* g_net2 = (const float*)d_in[17];
    const float* b_net2 = (const float*)d_in[18];

    float* vb;  cudaGetSymbolAddress((void**)&vb,  g_v);
    float* ctx; cudaGetSymbolAddress((void**)&ctx, g_ctx);
    float* tmp; cudaGetSymbolAddress((void**)&tmp, g_tmp);
    float* hb;  cudaGetSymbolAddress((void**)&hb,  g_h);
    float* hhb; cudaGetSymbolAddress((void**)&hhb, g_hh);
    __nv_bfloat16 *qhi, *qlo, *khi, *klo;
    cudaGetSymbolAddress((void**)&qhi, g_qhi);
    cudaGetSymbolAddress((void**)&qlo, g_qlo);
    cudaGetSymbolAddress((void**)&khi, g_khi);
    cudaGetSymbolAddress((void**)&klo, g_klo);
    __nv_bfloat16 *wqt_h, *wqt_l, *wkt_h, *wkt_l, *wvt_h, *wvt_l, *wot_h, *wot_l;
    __nv_bfloat16 *w2t_h, *w2t_l, *vt_h, *vt_l;
    cudaGetSymbolAddress((void**)&wqt_h, g_wqt_h);
    cudaGetSymbolAddress((void**)&wqt_l, g_wqt_l);
    cudaGetSymbolAddress((void**)&wkt_h, g_wkt_h);
    cudaGetSymbolAddress((void**)&wkt_l, g_wkt_l);
    cudaGetSymbolAddress((void**)&wvt_h, g_wvt_h);
    cudaGetSymbolAddress((void**)&wvt_l, g_wvt_l);
    cudaGetSymbolAddress((void**)&wot_h, g_wot_h);
    cudaGetSymbolAddress((void**)&wot_l, g_wot_l);
    cudaGetSymbolAddress((void**)&w2t_h, g_w2t_h);
    cudaGetSymbolAddress((void**)&w2t_l, g_w2t_l);
    cudaGetSymbolAddress((void**)&vt_h,  g_vt_h);
    cudaGetSymbolAddress((void**)&vt_l,  g_vt_l);

    const size_t OUT_ELEMS = (size_t)BB * SS * DD;
    float* outp = (float*)d_out;
    float* atnp = (float*)d_out + OUT_ELEMS;

    cudaFuncSetAttribute(attn_fused, cudaFuncAttributeMaxDynamicSharedMemorySize, AT_SMEM);

    // weight split-transpose
    dim3 gswt(DD / 64, DD / 64);
    split_wt<<<gswt, 256>>>(Wq, wqt_h, wqt_l, DD, DD);
    split_wt<<<gswt, 256>>>(Wk, wkt_h, wkt_l, DD, DD);
    split_wt<<<gswt, 256>>>(Wv, wvt_h, wvt_l, DD, DD);
    split_wt<<<gswt, 256>>>(Wo, wot_h, wot_l, DD, DD);
    split_wt<<<dim3(FF / 64, DD / 64), 256>>>(W2, w2t_h, w2t_l, FF, DD);

    // projections (HMMA); Q/K write bf16 hi/lo directly (Q pre-scaled 1/8)
    dim3 gproj(DD / 128, MT / 128);
    gemm_hmma_qk<<<gproj, 256>>>(x, wqt_h, wqt_l, bq, qhi, qlo, MT, DD, DD, 0.125f);
    gemm_hmma_qk<<<gproj, 256>>>(x, wkt_h, wkt_l, bk, khi, klo, MT, DD, DD, 1.0f);
    gemm_hmma<<<gproj, 256>>>(x, wvt_h, wvt_l, bv, vb, MT, DD, DD);

    v_split_t<<<dim3(BB * HH, SS / 64), 256>>>(vb, vt_h, vt_l);

    // fused attention: scores + softmax + prob write + ctx
    dim3 gattn(SS / 128, BB * HH);   // 16 x 32
    attn_fused<<<gattn, 256, AT_SMEM>>>(qhi, qlo, khi, klo, vt_h, vt_l, atnp, ctx);

    gemm_hmma<<<gproj, 256>>>(ctx, wot_h, wot_l, bo, tmp, MT, DD, DD);

    addln2_kernel<<<MT, 256>>>(tmp, x, g_mha, b_mha, g_net1, b_net1, hb);

    ffn1_gemm<<<MT / 128, 256>>>(hb, W1, b1, hhb);

    gemm_hmma<<<gproj, 256>>>(hhb, w2t_h, w2t_l, b2, tmp, MT, DD, FF);

    addln1_kernel<<<MT, 256>>>(tmp, hb, g_net2, b_net2, outp);
}